// round 2
// baseline (speedup 1.0000x reference)
#include <cuda_runtime.h>
#include <math.h>

#define BB  64
#define WW  128
#define KK  64
#define KSZ 7
#define EFD 128
#define ETD 128
#define HH  256
#define FHD 256
#define G3  768   // 3*H
#define ZC  192   // 3*K

// ---------------- scratch (static device globals; no runtime alloc) ----------------
__device__ __align__(16) float g_y[BB*WW*KK];
__device__ float g_s1[BB*KK];
__device__ float g_s2[BB*KK];
__device__ __align__(16) float g_hfeat[BB*WW*KK];
__device__ __align__(16) float g_htemp[BB*WW*KK];
__device__ __align__(16) float g_p[BB*WW*ETD];
__device__ __align__(16) float g_q[BB*WW*ETD];
__device__ __align__(16) float g_gi[BB*WW*G3];
__device__ float g_h[BB*HH];
__device__ __align__(16) float g_cwT[KSZ*KK*KK];   // [s][i][k]
__device__ __align__(16) float g_tlwT[ETD*ETD];    // [c][e]
__device__ __align__(16) float g_wihT[ZC*G3];      // [c][o]
__device__ __align__(16) float g_whhT[HH*G3];      // [j][o]
__device__ __align__(16) float g_fc0T[FHD*FHD];
__device__ __align__(16) float g_fc1T[FHD*FHD];
__device__ __align__(16) float g_fc2T[FHD*FHD];
__device__ __align__(16) float g_fc3T[FHD*KK];
__device__ float g_u1[WW];
__device__ float g_u2[WW];
__device__ float g_c12[2];

__device__ __forceinline__ float sigm(float x){ return 1.f/(1.f+__expf(-x)); }
__device__ __forceinline__ float lrelu(float v){ return fmaxf(v, 0.2f*v); } // ALPHA=0.2<1

// ---------------- weight reshapes / transposes ----------------
__global__ void k_prep(const float* __restrict__ conv_w, const float* __restrict__ tlw,
                       const float* __restrict__ wih, const float* __restrict__ whh,
                       const float* __restrict__ fc0, const float* __restrict__ fc1,
                       const float* __restrict__ fc2, const float* __restrict__ fc3){
    int idx = blockIdx.x*blockDim.x + threadIdx.x;
    // conv_w: (64,64,7) -> [s][i][k]
    if(idx < 28672){
        int k = idx/448; int rem = idx - k*448; int i = rem/7; int s = rem - i*7;
        g_cwT[(s*64+i)*64 + k] = conv_w[idx];
        return;
    }
    idx -= 28672;
    if(idx < 16384){ // temp_lin_w (128,128) -> [c][e]
        int e = idx>>7, c = idx&127;
        g_tlwT[c*128 + e] = tlw[idx];
        return;
    }
    idx -= 16384;
    if(idx < 147456){ // gru_wih (768,192) -> [c][o]
        int o = idx/192, c = idx - o*192;
        g_wihT[c*768 + o] = wih[idx];
        return;
    }
    idx -= 147456;
    if(idx < 196608){ // gru_whh (768,256) -> [j][o]
        int o = idx>>8, j = idx&255;
        g_whhT[j*768 + o] = whh[idx];
        return;
    }
    idx -= 196608;
    if(idx < 65536){ int o = idx>>8, j = idx&255; g_fc0T[j*256+o] = fc0[idx]; return; }
    idx -= 65536;
    if(idx < 65536){ int o = idx>>8, j = idx&255; g_fc1T[j*256+o] = fc1[idx]; return; }
    idx -= 65536;
    if(idx < 65536){ int o = idx>>8, j = idx&255; g_fc2T[j*256+o] = fc2[idx]; return; }
    idx -= 65536;
    if(idx < 16384){ int o = idx>>8, j = idx&255; g_fc3T[j*64+o] = fc3[idx]; return; } // fc3 (64,256)
}

// u1[w] = sum_e flw[e,w]*fa[e];  u2 with fa[EF+e];  c1/c2 from bias (linearity of s1/s2)
__global__ void k_u(const float* __restrict__ flw, const float* __restrict__ flb,
                    const float* __restrict__ fa){
    int t = threadIdx.x; // 128
    float a1=0.f, a2=0.f;
    for(int e=0;e<EFD;e++){ float w = flw[e*WW + t]; a1 += w*fa[e]; a2 += w*fa[EFD+e]; }
    g_u1[t]=a1; g_u2[t]=a2;
    if(t==0){ float c=0.f; for(int e=0;e<EFD;e++) c += flb[e]*fa[e];     g_c12[0]=c; }
    if(t==1){ float c=0.f; for(int e=0;e<EFD;e++) c += flb[e]*fa[EFD+e]; g_c12[1]=c; }
}

// ---------------- conv1d (pad=3) + relu -> y[b,w,k] ----------------
__global__ void k_conv(const float* __restrict__ x, const float* __restrict__ conv_b){
    int b = blockIdx.y; int w0 = blockIdx.x*4;
    int t = threadIdx.x; // 64 (= k)
    __shared__ float xs[10*64];
    #pragma unroll
    for(int r=0;r<10;r++){
        int row = w0-3+r;
        xs[r*64+t] = (row>=0 && row<WW) ? x[(b*WW+row)*KK + t] : 0.f;
    }
    __syncthreads();
    float bias = conv_b[t];
    float a0=bias, a1=bias, a2=bias, a3=bias;
    #pragma unroll
    for(int s=0;s<KSZ;s++){
        #pragma unroll 8
        for(int i=0;i<KK;i++){
            float cw = g_cwT[(s*64+i)*64 + t];
            a0 += xs[(s+0)*64+i]*cw;
            a1 += xs[(s+1)*64+i]*cw;
            a2 += xs[(s+2)*64+i]*cw;
            a3 += xs[(s+3)*64+i]*cw;
        }
    }
    g_y[(b*WW+w0+0)*KK+t] = fmaxf(a0,0.f);
    g_y[(b*WW+w0+1)*KK+t] = fmaxf(a1,0.f);
    g_y[(b*WW+w0+2)*KK+t] = fmaxf(a2,0.f);
    g_y[(b*WW+w0+3)*KK+t] = fmaxf(a3,0.f);
}

// ---------------- s1,s2 (collapsed Wx GEMM) ----------------
__global__ void k_s(void){
    int b = blockIdx.x; int t = threadIdx.x; // 64
    __shared__ float u1s[WW], u2s[WW];
    u1s[t]=g_u1[t]; u1s[t+64]=g_u1[t+64];
    u2s[t]=g_u2[t]; u2s[t+64]=g_u2[t+64];
    __syncthreads();
    float a1 = g_c12[0], a2 = g_c12[1];
    #pragma unroll 8
    for(int w=0;w<WW;w++){
        float yv = g_y[(b*WW+w)*KK + t];
        a1 += yv*u1s[w]; a2 += yv*u2s[w];
    }
    g_s1[b*KK+t]=a1; g_s2[b*KK+t]=a2;
}

// ---------------- feature attention + h_feat ----------------
__global__ void k_feat(const float* __restrict__ feat_bias){
    int b = blockIdx.x; int t = threadIdx.x; // 128
    __shared__ float ys[WW*KK];    // 32KB  ys[w*64+j]
    __shared__ float att[KK*KK];   // 16KB  att[j*64+i]
    for(int it=0; it<64; it++){ int idx = it*128+t; ys[idx] = g_y[b*WW*KK + idx]; }
    __syncthreads();
    int lane = t&31, wd = t>>5;
    for(int r=0;r<16;r++){
        int i = wd*16 + r;
        float s1v = g_s1[b*64+i];
        int j0 = lane, j1 = lane+32;
        float v0 = lrelu(s1v + g_s2[b*64+j0]) + feat_bias[i*64+j0];
        float v1 = lrelu(s1v + g_s2[b*64+j1]) + feat_bias[i*64+j1];
        float m = fmaxf(v0,v1);
        #pragma unroll
        for(int off=16;off;off>>=1) m = fmaxf(m, __shfl_xor_sync(0xffffffffu, m, off));
        float e0 = __expf(v0-m), e1 = __expf(v1-m);
        float ssum = e0+e1;
        #pragma unroll
        for(int off=16;off;off>>=1) ssum += __shfl_xor_sync(0xffffffffu, ssum, off);
        float inv = 1.f/ssum;
        att[j0*64+i] = e0*inv;
        att[j1*64+i] = e1*inv;
    }
    __syncthreads();
    int i = t&63, wofs = t>>6;
    for(int wl=0; wl<64; wl++){
        int w = wl*2 + wofs;
        float acc = 0.f;
        #pragma unroll 8
        for(int j=0;j<64;j++) acc += att[j*64+i]*ys[w*64+j];
        g_hfeat[(b*WW+w)*KK + i] = sigm(acc);
    }
}

// ---------------- p,q (temp_lin_b folded into p) ----------------
__global__ void k_pq(const float* __restrict__ tlb){
    int b = blockIdx.y; int w0 = blockIdx.x*8; int t = threadIdx.x; // 128 (= e)
    __shared__ float ys[8*64];
    #pragma unroll
    for(int r=0;r<4;r++){ int idx = r*128+t; ys[idx] = g_y[(b*WW+w0)*KK + idx]; }
    __syncthreads();
    float pb = tlb[t];
    float ap[8], aq[8];
    #pragma unroll
    for(int r=0;r<8;r++){ ap[r]=pb; aq[r]=0.f; }
    for(int c=0;c<64;c++){
        float wp = g_tlwT[c*ETD + t];
        float wq = g_tlwT[(64+c)*ETD + t];
        #pragma unroll
        for(int r=0;r<8;r++){ float yv = ys[r*64+c]; ap[r]+=yv*wp; aq[r]+=yv*wq; }
    }
    #pragma unroll
    for(int r=0;r<8;r++){
        g_p[(b*WW+w0+r)*ETD + t] = ap[r];
        g_q[(b*WW+w0+r)*ETD + t] = aq[r];
    }
}

// ---------------- temporal attention + h_temp ----------------
__global__ void k_temp(const float* __restrict__ temp_a, const float* __restrict__ temp_bias){
    int b = blockIdx.y; int i = blockIdx.x; int t = threadIdx.x; // 128 (= j)
    __shared__ float ps[ETD], tas[ETD], red[128], att[WW];
    ps[t]  = g_p[(b*WW+i)*ETD + t];
    tas[t] = temp_a[t];
    __syncthreads();
    const float4* q4 = (const float4*)(g_q + (size_t)(b*WW+t)*ETD);
    float ej = 0.f;
    #pragma unroll 8
    for(int e4=0;e4<32;e4++){
        float4 qv = q4[e4];
        int e = e4*4;
        float v;
        v = ps[e+0]+qv.x; v = lrelu(v); ej += v*tas[e+0];
        v = ps[e+1]+qv.y; v = lrelu(v); ej += v*tas[e+1];
        v = ps[e+2]+qv.z; v = lrelu(v); ej += v*tas[e+2];
        v = ps[e+3]+qv.w; v = lrelu(v); ej += v*tas[e+3];
    }
    ej += temp_bias[i*WW + t];
    // softmax over the 128 threads
    red[t] = ej; __syncthreads();
    for(int off=64;off;off>>=1){ if(t<off) red[t]=fmaxf(red[t],red[t+off]); __syncthreads(); }
    float mx = red[0]; __syncthreads();
    float ex = __expf(ej - mx);
    red[t] = ex; __syncthreads();
    for(int off=64;off;off>>=1){ if(t<off) red[t]+=red[t+off]; __syncthreads(); }
    float inv = 1.f/red[0];
    att[t] = ex*inv;
    __syncthreads();
    // h_temp[b,i,k] = sigmoid(sum_j att[j]*y[b,j,k]) ; 2 threads per k
    int k = t&63, half = t>>6;
    float acc = 0.f;
    #pragma unroll 8
    for(int j=0;j<64;j++){
        int jj = half*64 + j;
        acc += att[jj]*g_y[(b*WW+jj)*KK + k];
    }
    __syncthreads();
    red[t] = acc; __syncthreads();
    if(t<64){
        float v = red[t] + red[t+64];
        g_htemp[(b*WW+i)*KK + t] = sigm(v);
    }
}

// ---------------- gi = Z @ wih^T + bih  (Z gathered from y/hfeat/htemp) ----------------
__global__ __launch_bounds__(256) void k_gi(const float* __restrict__ bih){
    int m0 = blockIdx.x*16; int t = threadIdx.x; // 256
    __shared__ float zs[16*ZC];
    #pragma unroll
    for(int it=0; it<12; it++){
        int idx = it*256 + t;                // 3072 total
        int r = idx/ZC, c = idx - r*ZC;
        int m = m0 + r; int bb = m>>7; int tt = m&127;
        int base = (bb*WW+tt)*KK;
        float v;
        if(c < 64)       v = g_y[base + c];
        else if(c < 128) v = g_hfeat[base + c-64];
        else             v = g_htemp[base + c-128];
        zs[idx] = v;
    }
    __syncthreads();
    #pragma unroll
    for(int chunk=0; chunk<3; chunk++){
        int col = chunk*256 + t;
        float bv = bih[col];
        float acc[16];
        #pragma unroll
        for(int r=0;r<16;r++) acc[r] = bv;
        for(int c=0;c<ZC;c++){
            float wv = g_wihT[c*G3 + col];
            #pragma unroll
            for(int r=0;r<16;r++) acc[r] += zs[r*ZC + c]*wv;
        }
        #pragma unroll
        for(int r=0;r<16;r++) g_gi[(size_t)(m0+r)*G3 + col] = acc[r];
    }
}

// ---------------- GRU: 64 persistent CTAs (one per batch), no cross-CTA sync ----------------
__global__ __launch_bounds__(192) void k_gru(const float* __restrict__ bhh){
    int b = blockIdx.x; int t = threadIdx.x; // 192 ; thread owns outputs 4t..4t+3
    __shared__ float hs[HH];
    __shared__ __align__(16) float ghs[G3];
    for(int idx=t; idx<HH; idx+=192) hs[idx] = 0.f;
    float b0 = bhh[4*t+0], b1 = bhh[4*t+1], b2 = bhh[4*t+2], b3 = bhh[4*t+3];
    const float4* wT4 = (const float4*)g_whhT;   // [j][o/4]
    __syncthreads();
    for(int step=0; step<WW; step++){
        float a0=b0, a1=b1, a2=b2, a3=b3;
        #pragma unroll 4
        for(int j=0;j<HH;j++){
            float hj = hs[j];
            float4 wv = wT4[j*(G3/4) + t];
            a0 += wv.x*hj; a1 += wv.y*hj; a2 += wv.z*hj; a3 += wv.w*hj;
        }
        *((float4*)(ghs + 4*t)) = make_float4(a0,a1,a2,a3);
        __syncthreads();                 // gh visible AND all hs reads done
        if(t < 64){
            const float4* gi4 = (const float4*)(g_gi + (size_t)(b*WW+step)*G3);
            float4 gr = gi4[t], gz = gi4[64+t], gn = gi4[128+t];
            float gir[4] = {gr.x,gr.y,gr.z,gr.w};
            float giz[4] = {gz.x,gz.y,gz.z,gz.w};
            float gin[4] = {gn.x,gn.y,gn.z,gn.w};
            #pragma unroll
            for(int d=0;d<4;d++){
                int m = 4*t+d;
                float r  = sigm(gir[d] + ghs[m]);
                float zg = sigm(giz[d] + ghs[256+m]);
                float n  = tanhf(gin[d] + r*ghs[512+m]);
                hs[m] = n + zg*(hs[m] - n);
            }
        }
        __syncthreads();
    }
    for(int idx=t; idx<HH; idx+=192) g_h[b*HH + idx] = hs[idx];
}

// ---------------- MLP head ----------------
__global__ void k_mlp(const float* __restrict__ b0, const float* __restrict__ b1,
                      const float* __restrict__ b2, const float* __restrict__ b3,
                      float* __restrict__ out){
    int b = blockIdx.x; int t = threadIdx.x; // 256
    __shared__ float va[FHD], vb[FHD];
    va[t] = g_h[b*HH + t];
    __syncthreads();
    float acc = b0[t];
    #pragma unroll 8
    for(int j=0;j<HH;j++) acc += va[j]*g_fc0T[j*FHD + t];
    vb[t] = fmaxf(acc, 0.f);
    __syncthreads();
    acc = b1[t];
    #pragma unroll 8
    for(int j=0;j<FHD;j++) acc += vb[j]*g_fc1T[j*FHD + t];
    va[t] = fmaxf(acc, 0.f);
    __syncthreads();
    acc = b2[t];
    #pragma unroll 8
    for(int j=0;j<FHD;j++) acc += va[j]*g_fc2T[j*FHD + t];
    vb[t] = fmaxf(acc, 0.f);
    __syncthreads();
    if(t < 64){
        float a = b3[t];
        #pragma unroll 8
        for(int j=0;j<FHD;j++) a += vb[j]*g_fc3T[j*64 + t];
        out[b*64 + t] = a;
    }
}

// ---------------- launch ----------------
extern "C" void kernel_launch(void* const* d_in, const int* in_sizes, int n_in,
                              void* d_out, int out_size){
    const float* x        = (const float*)d_in[0];
    const float* conv_w   = (const float*)d_in[1];
    const float* conv_b   = (const float*)d_in[2];
    const float* flw      = (const float*)d_in[3];
    const float* flb      = (const float*)d_in[4];
    const float* fa       = (const float*)d_in[5];
    const float* fbias    = (const float*)d_in[6];
    const float* tlw      = (const float*)d_in[7];
    const float* tlb      = (const float*)d_in[8];
    const float* ta       = (const float*)d_in[9];
    const float* tbias    = (const float*)d_in[10];
    const float* wih      = (const float*)d_in[11];
    const float* whh      = (const float*)d_in[12];
    const float* bih      = (const float*)d_in[13];
    const float* bhh      = (const float*)d_in[14];
    const float* fc0_w    = (const float*)d_in[15];
    const float* fc0_b    = (const float*)d_in[16];
    const float* fc1_w    = (const float*)d_in[17];
    const float* fc1_b    = (const float*)d_in[18];
    const float* fc2_w    = (const float*)d_in[19];
    const float* fc2_b    = (const float*)d_in[20];
    const float* fc3_w    = (const float*)d_in[21];
    const float* fc3_b    = (const float*)d_in[22];
    float* out = (float*)d_out;

    k_prep<<<2352, 256>>>(conv_w, tlw, wih, whh, fc0_w, fc1_w, fc2_w, fc3_w);
    k_u<<<1, 128>>>(flw, flb, fa);
    k_conv<<<dim3(32, 64), 64>>>(x, conv_b);
    k_s<<<64, 64>>>();
    k_feat<<<64, 128>>>(fbias);
    k_pq<<<dim3(16, 64), 128>>>(tlb);
    k_temp<<<dim3(128, 64), 128>>>(ta, tbias);
    k_gi<<<512, 256>>>(bih);
    k_gru<<<64, 192>>>(bhh);
    k_mlp<<<64, 256>>>(fc0_b, fc1_b, fc2_b, fc3_b, out);
}

// round 3
// speedup vs baseline: 1.7183x; 1.7183x over previous
#include <cuda_runtime.h>
#include <math.h>

#define BB  64
#define WW  128
#define KK  64
#define KSZ 7
#define EFD 128
#define ETD 128
#define HH  256
#define FHD 256
#define G3  768   // 3*H
#define ZC  192   // 3*K

// ---------------- scratch (static device globals; no runtime alloc) ----------------
__device__ __align__(16) float g_y[BB*WW*KK];
__device__ float g_s1[BB*KK];
__device__ float g_s2[BB*KK];
__device__ __align__(16) float g_hfeat[BB*WW*KK];
__device__ __align__(16) float g_htemp[BB*WW*KK];
__device__ __align__(16) float g_p[BB*WW*ETD];
__device__ __align__(16) float g_q[BB*WW*ETD];
__device__ __align__(16) float g_gi[BB*WW*G3];
__device__ float g_h[BB*HH];
__device__ __align__(16) float g_cwT[KSZ*KK*KK];   // [s][i][k]
__device__ __align__(16) float g_tlwT[ETD*ETD];    // [c][e]
__device__ __align__(16) float g_wihT[ZC*G3];      // [c][o]
__device__ __align__(16) float g_whhS[4*HH*192];   // [slice][j][192 gate-rows]
__device__ __align__(16) float g_hbuf[2*32*512];   // double-buffered h exchange
__device__ unsigned g_cnt[32];                     // per-group step counters
__device__ __align__(16) float g_fc0T[FHD*FHD];
__device__ __align__(16) float g_fc1T[FHD*FHD];
__device__ __align__(16) float g_fc2T[FHD*FHD];
__device__ __align__(16) float g_fc3T[FHD*KK];
__device__ float g_u1[WW];
__device__ float g_u2[WW];
__device__ float g_c12[2];

__device__ __forceinline__ float sigm(float x){ return 1.f/(1.f+__expf(-x)); }
__device__ __forceinline__ float lrelu(float v){ return fmaxf(v, 0.2f*v); } // ALPHA=0.2<1

// ---------------- weight reshapes / transposes ----------------
__global__ void k_prep(const float* __restrict__ conv_w, const float* __restrict__ tlw,
                       const float* __restrict__ wih, const float* __restrict__ whh,
                       const float* __restrict__ fc0, const float* __restrict__ fc1,
                       const float* __restrict__ fc2, const float* __restrict__ fc3){
    if(blockIdx.x==0 && threadIdx.x<32) g_cnt[threadIdx.x] = 0u;   // reset spin counters
    int idx = blockIdx.x*blockDim.x + threadIdx.x;
    // conv_w: (64,64,7) -> [s][i][k]
    if(idx < 28672){
        int k = idx/448; int rem = idx - k*448; int i = rem/7; int s = rem - i*7;
        g_cwT[(s*64+i)*64 + k] = conv_w[idx];
        return;
    }
    idx -= 28672;
    if(idx < 16384){ // temp_lin_w (128,128) -> [c][e]
        int e = idx>>7, c = idx&127;
        g_tlwT[c*128 + e] = tlw[idx];
        return;
    }
    idx -= 16384;
    if(idx < 147456){ // gru_wih (768,192) -> [c][o]
        int o = idx/192, c = idx - o*192;
        g_wihT[c*768 + o] = wih[idx];
        return;
    }
    idx -= 147456;
    if(idx < 196608){ // gru_whh (768,256) -> slice layout [s][j][g*64+ol]
        int o = idx>>8, j = idx&255;
        int g = o>>8;         // gate 0..2
        int ow = o&255;       // hidden unit
        int s = ow>>6, ol = ow&63;
        g_whhS[((s*256 + j)*192) + g*64 + ol] = whh[idx];
        return;
    }
    idx -= 196608;
    if(idx < 65536){ int o = idx>>8, j = idx&255; g_fc0T[j*256+o] = fc0[idx]; return; }
    idx -= 65536;
    if(idx < 65536){ int o = idx>>8, j = idx&255; g_fc1T[j*256+o] = fc1[idx]; return; }
    idx -= 65536;
    if(idx < 65536){ int o = idx>>8, j = idx&255; g_fc2T[j*256+o] = fc2[idx]; return; }
    idx -= 65536;
    if(idx < 16384){ int o = idx>>8, j = idx&255; g_fc3T[j*64+o] = fc3[idx]; return; } // fc3 (64,256)
}

// u1[w] = sum_e flw[e,w]*fa[e];  u2 with fa[EF+e];  c1/c2 from bias (linearity of s1/s2)
__global__ void k_u(const float* __restrict__ flw, const float* __restrict__ flb,
                    const float* __restrict__ fa){
    int t = threadIdx.x; // 128
    float a1=0.f, a2=0.f;
    for(int e=0;e<EFD;e++){ float w = flw[e*WW + t]; a1 += w*fa[e]; a2 += w*fa[EFD+e]; }
    g_u1[t]=a1; g_u2[t]=a2;
    if(t==0){ float c=0.f; for(int e=0;e<EFD;e++) c += flb[e]*fa[e];     g_c12[0]=c; }
    if(t==1){ float c=0.f; for(int e=0;e<EFD;e++) c += flb[e]*fa[EFD+e]; g_c12[1]=c; }
}

// ---------------- conv1d (pad=3) + relu -> y[b,w,k] ----------------
__global__ void k_conv(const float* __restrict__ x, const float* __restrict__ conv_b){
    int b = blockIdx.y; int w0 = blockIdx.x*4;
    int t = threadIdx.x; // 64 (= k)
    __shared__ float xs[10*64];
    #pragma unroll
    for(int r=0;r<10;r++){
        int row = w0-3+r;
        xs[r*64+t] = (row>=0 && row<WW) ? x[(b*WW+row)*KK + t] : 0.f;
    }
    __syncthreads();
    float bias = conv_b[t];
    float a0=bias, a1=bias, a2=bias, a3=bias;
    #pragma unroll
    for(int s=0;s<KSZ;s++){
        #pragma unroll 8
        for(int i=0;i<KK;i++){
            float cw = g_cwT[(s*64+i)*64 + t];
            a0 += xs[(s+0)*64+i]*cw;
            a1 += xs[(s+1)*64+i]*cw;
            a2 += xs[(s+2)*64+i]*cw;
            a3 += xs[(s+3)*64+i]*cw;
        }
    }
    g_y[(b*WW+w0+0)*KK+t] = fmaxf(a0,0.f);
    g_y[(b*WW+w0+1)*KK+t] = fmaxf(a1,0.f);
    g_y[(b*WW+w0+2)*KK+t] = fmaxf(a2,0.f);
    g_y[(b*WW+w0+3)*KK+t] = fmaxf(a3,0.f);
}

// ---------------- s1,s2 (collapsed Wx GEMM) ----------------
__global__ void k_s(void){
    int b = blockIdx.x; int t = threadIdx.x; // 256
    __shared__ float u1s[WW], u2s[WW], r1[256], r2[256];
    if(t<128){ u1s[t]=g_u1[t]; u2s[t]=g_u2[t]; }
    __syncthreads();
    int k = t&63, wq = t>>6;
    float a1=0.f, a2=0.f;
    #pragma unroll 8
    for(int w=wq*32; w<wq*32+32; w++){
        float yv = g_y[(b*WW+w)*KK + k];
        a1 += yv*u1s[w]; a2 += yv*u2s[w];
    }
    r1[t]=a1; r2[t]=a2;
    __syncthreads();
    if(t<64){
        g_s1[b*KK+t] = r1[t]+r1[t+64]+r1[t+128]+r1[t+192] + g_c12[0];
        g_s2[b*KK+t] = r2[t]+r2[t+64]+r2[t+128]+r2[t+192] + g_c12[1];
    }
}

// ---------------- feature attention + h_feat ----------------
__global__ void k_feat(const float* __restrict__ feat_bias){
    int b = blockIdx.x; int t = threadIdx.x; // 128
    __shared__ float ys[WW*KK];    // 32KB  ys[w*64+j]
    __shared__ float att[KK*KK];   // 16KB  att[j*64+i]
    for(int it=0; it<64; it++){ int idx = it*128+t; ys[idx] = g_y[b*WW*KK + idx]; }
    __syncthreads();
    int lane = t&31, wd = t>>5;
    for(int r=0;r<16;r++){
        int i = wd*16 + r;
        float s1v = g_s1[b*64+i];
        int j0 = lane, j1 = lane+32;
        float v0 = lrelu(s1v + g_s2[b*64+j0]) + feat_bias[i*64+j0];
        float v1 = lrelu(s1v + g_s2[b*64+j1]) + feat_bias[i*64+j1];
        float m = fmaxf(v0,v1);
        #pragma unroll
        for(int off=16;off;off>>=1) m = fmaxf(m, __shfl_xor_sync(0xffffffffu, m, off));
        float e0 = __expf(v0-m), e1 = __expf(v1-m);
        float ssum = e0+e1;
        #pragma unroll
        for(int off=16;off;off>>=1) ssum += __shfl_xor_sync(0xffffffffu, ssum, off);
        float inv = 1.f/ssum;
        att[j0*64+i] = e0*inv;
        att[j1*64+i] = e1*inv;
    }
    __syncthreads();
    int i = t&63, wofs = t>>6;
    for(int wl=0; wl<64; wl++){
        int w = wl*2 + wofs;
        float acc = 0.f;
        #pragma unroll 8
        for(int j=0;j<64;j++) acc += att[j*64+i]*ys[w*64+j];
        g_hfeat[(b*WW+w)*KK + i] = sigm(acc);
    }
}

// ---------------- p,q (temp_lin_b folded into p) ----------------
__global__ void k_pq(const float* __restrict__ tlb){
    int b = blockIdx.y; int w0 = blockIdx.x*8; int t = threadIdx.x; // 128 (= e)
    __shared__ float ys[8*64];
    #pragma unroll
    for(int r=0;r<4;r++){ int idx = r*128+t; ys[idx] = g_y[(b*WW+w0)*KK + idx]; }
    __syncthreads();
    float pb = tlb[t];
    float ap[8], aq[8];
    #pragma unroll
    for(int r=0;r<8;r++){ ap[r]=pb; aq[r]=0.f; }
    for(int c=0;c<64;c++){
        float wp = g_tlwT[c*ETD + t];
        float wq = g_tlwT[(64+c)*ETD + t];
        #pragma unroll
        for(int r=0;r<8;r++){ float yv = ys[r*64+c]; ap[r]+=yv*wp; aq[r]+=yv*wq; }
    }
    #pragma unroll
    for(int r=0;r<8;r++){
        g_p[(b*WW+w0+r)*ETD + t] = ap[r];
        g_q[(b*WW+w0+r)*ETD + t] = aq[r];
    }
}

// ---------------- temporal attention + h_temp (8 i's per block) ----------------
__global__ void k_temp(const float* __restrict__ temp_a, const float* __restrict__ temp_bias){
    int i0 = blockIdx.x*8; int b = blockIdx.y; int t = threadIdx.x; // 128 (= j)
    __shared__ __align__(16) float psst[8*128];
    __shared__ float tass[128];
    __shared__ __align__(16) float atts[128*8];
    __shared__ float wr[8*4];
    __shared__ float hb[64*8];
    tass[t] = temp_a[t];
    #pragma unroll
    for(int r=0;r<8;r++) psst[r*128+t] = g_p[(b*WW+i0+r)*ETD + t];
    __syncthreads();
    const float4* q4 = (const float4*)(g_q + (size_t)(b*WW+t)*ETD);
    float ej[8];
    #pragma unroll
    for(int i=0;i<8;i++) ej[i] = temp_bias[(i0+i)*WW + t];
    for(int c=0;c<32;c++){
        float4 qv = q4[c];
        float ta0=tass[4*c], ta1=tass[4*c+1], ta2=tass[4*c+2], ta3=tass[4*c+3];
        #pragma unroll
        for(int i=0;i<8;i++){
            const float* pp = psst + i*128 + 4*c;
            float v;
            v = pp[0]+qv.x; ej[i] += lrelu(v)*ta0;
            v = pp[1]+qv.y; ej[i] += lrelu(v)*ta1;
            v = pp[2]+qv.z; ej[i] += lrelu(v)*ta2;
            v = pp[3]+qv.w; ej[i] += lrelu(v)*ta3;
        }
    }
    int lane = t&31, wd = t>>5;
    // block max per i
    #pragma unroll
    for(int i=0;i<8;i++){
        float m = ej[i];
        #pragma unroll
        for(int off=16;off;off>>=1) m = fmaxf(m, __shfl_xor_sync(0xffffffffu, m, off));
        if(lane==0) wr[i*4+wd]=m;
    }
    __syncthreads();
    float mx[8];
    #pragma unroll
    for(int i=0;i<8;i++) mx[i] = fmaxf(fmaxf(wr[i*4],wr[i*4+1]), fmaxf(wr[i*4+2],wr[i*4+3]));
    __syncthreads();
    // exp + block sum per i
    #pragma unroll
    for(int i=0;i<8;i++){
        float e = __expf(ej[i]-mx[i]); ej[i]=e;
        float ss = e;
        #pragma unroll
        for(int off=16;off;off>>=1) ss += __shfl_xor_sync(0xffffffffu, ss, off);
        if(lane==0) wr[i*4+wd]=ss;
    }
    __syncthreads();
    #pragma unroll
    for(int i=0;i<8;i++){
        float ss = wr[i*4]+wr[i*4+1]+wr[i*4+2]+wr[i*4+3];
        atts[t*8+i] = ej[i]/ss;
    }
    __syncthreads();
    // h_temp: out[b][i0+i][k] = sigm(sum_j att[i][j]*y[b][j][k])
    int k = t&63, half = t>>6;
    float acc[8];
    #pragma unroll
    for(int i=0;i<8;i++) acc[i]=0.f;
    for(int j=0;j<64;j++){
        int jj = half*64+j;
        float yv = g_y[(b*WW+jj)*KK + k];
        const float4* a4 = (const float4*)(atts + jj*8);
        float4 aA = a4[0], aB = a4[1];
        acc[0]+=aA.x*yv; acc[1]+=aA.y*yv; acc[2]+=aA.z*yv; acc[3]+=aA.w*yv;
        acc[4]+=aB.x*yv; acc[5]+=aB.y*yv; acc[6]+=aB.z*yv; acc[7]+=aB.w*yv;
    }
    if(half==1){
        #pragma unroll
        for(int i=0;i<8;i++) hb[k*8+i]=acc[i];
    }
    __syncthreads();
    if(half==0){
        #pragma unroll
        for(int i=0;i<8;i++){
            float v = acc[i] + hb[k*8+i];
            g_htemp[(b*WW+i0+i)*KK + k] = sigm(v);
        }
    }
}

// ---------------- gi = Z @ wih^T + bih  (packed f32x2 FMA) ----------------
__global__ __launch_bounds__(256) void k_gi(const float* __restrict__ bih){
    int m0 = blockIdx.x*16; int t = threadIdx.x; // 256
    __shared__ __align__(16) float zs[ZC*18];    // [c][16 rows, pad 18]
    #pragma unroll
    for(int it=0; it<12; it++){
        int idx = it*256 + t;                // 3072 total
        int r = idx/ZC, c = idx - r*ZC;
        int m = m0 + r; int bb = m>>7; int tt = m&127;
        int base = (bb*WW+tt)*KK;
        float v;
        if(c < 64)       v = g_y[base + c];
        else if(c < 128) v = g_hfeat[base + c-64];
        else             v = g_htemp[base + c-128];
        zs[c*18 + r] = v;
    }
    __syncthreads();
    #pragma unroll
    for(int chunk=0; chunk<3; chunk++){
        int col = chunk*256 + t;
        float bv = bih[col];
        unsigned long long acc[8];
        unsigned long long bb2;
        asm("mov.b64 %0, {%1, %1};" : "=l"(bb2) : "r"(__float_as_uint(bv)));
        #pragma unroll
        for(int i=0;i<8;i++) acc[i] = bb2;
        for(int c=0;c<ZC;c++){
            float w = g_wihT[c*G3 + col];
            unsigned long long ww;
            asm("mov.b64 %0, {%1, %1};" : "=l"(ww) : "r"(__float_as_uint(w)));
            const unsigned long long* z2 = (const unsigned long long*)(zs + c*18);
            #pragma unroll
            for(int i=0;i<8;i++){
                asm("fma.rn.f32x2 %0, %1, %2, %0;" : "+l"(acc[i]) : "l"(ww), "l"(z2[i]));
            }
        }
        #pragma unroll
        for(int i=0;i<8;i++){
            unsigned lo, hi;
            asm("mov.b64 {%0, %1}, %2;" : "=r"(lo), "=r"(hi) : "l"(acc[i]));
            g_gi[(size_t)(m0+2*i  )*G3 + col] = __uint_as_float(lo);
            g_gi[(size_t)(m0+2*i+1)*G3 + col] = __uint_as_float(hi);
        }
    }
}

// ---------------- GRU: 32 groups x 4 L1-resident slices, 2 batches/CTA ----------------
__global__ __launch_bounds__(192) void k_gru(const float* __restrict__ bhh){
    int cta = blockIdx.x;      // 128
    int p = cta >> 2;          // batch-pair group
    int s = cta & 3;           // slice (hidden units 64s..64s+63, all 3 gates)
    int t = threadIdx.x;       // 192
    __shared__ __align__(16) float hs[512];          // [j][b] current h, both batches
    __shared__ float part[4*192*2];                  // [jg][gate-row][b]
    for(int i=t;i<512;i+=192) hs[i]=0.f;
    int jg = t/48, rg = t - jg*48;
    const float4* wbase = (const float4*)g_whhS + (size_t)s*256*48;
    int ol = t & 63, bsel = t >> 6;                  // gates role (t<128)
    float bhr=0.f, bhz=0.f, bhn=0.f;
    if(t<128){
        bhr = bhh[      64*s+ol];
        bhz = bhh[256 + 64*s+ol];
        bhn = bhh[512 + 64*s+ol];
    }
    __syncthreads();
    for(int step=0; step<WW; step++){
        float acc[8];
        #pragma unroll
        for(int i=0;i<8;i++) acc[i]=0.f;
        int jbase = jg*64;
        #pragma unroll 4
        for(int jj=0;jj<64;jj++){
            int j = jbase+jj;
            float4 wv = __ldg(wbase + j*48 + rg);
            float2 h2 = *(const float2*)(hs + j*2);
            acc[0] += wv.x*h2.x; acc[1] += wv.x*h2.y;
            acc[2] += wv.y*h2.x; acc[3] += wv.y*h2.y;
            acc[4] += wv.z*h2.x; acc[5] += wv.z*h2.y;
            acc[6] += wv.w*h2.x; acc[7] += wv.w*h2.y;
        }
        {
            int base = (jg*192 + 4*rg)*2;
            #pragma unroll
            for(int i=0;i<4;i++){ part[base + i*2] = acc[i*2]; part[base + i*2 + 1] = acc[i*2+1]; }
        }
        __syncthreads();
        if(t < 128){
            float ghr=bhr, ghz=bhz, ghn=bhn;
            #pragma unroll
            for(int g4=0; g4<4; g4++){
                ghr += part[(g4*192 +       ol)*2 + bsel];
                ghz += part[(g4*192 +  64 + ol)*2 + bsel];
                ghn += part[(g4*192 + 128 + ol)*2 + bsel];
            }
            const float* gib = g_gi + ((size_t)((2*p+bsel)*WW + step))*G3 + s*64 + ol;
            float gr = __ldcg(gib);
            float gz = __ldcg(gib+256);
            float gn = __ldcg(gib+512);
            float hold = hs[(64*s+ol)*2 + bsel];
            float r  = sigm(gr+ghr);
            float zg = sigm(gz+ghz);
            float n  = tanhf(gn + r*ghn);
            float hnew = n + zg*(hold - n);
            g_hbuf[((step&1)*32+p)*512 + (64*s+ol)*2 + bsel] = hnew;
            __threadfence();
        }
        __syncthreads();
        if(t==0){
            atomicAdd(&g_cnt[p], 1u);
            volatile unsigned* cc = &g_cnt[p];
            unsigned target = 4u*(unsigned)(step+1);
            while(*cc < target){}
            __threadfence();
        }
        __syncthreads();
        if(t<128){
            const float4* hb4 = (const float4*)(g_hbuf + ((step&1)*32+p)*512);
            float4 v = __ldcg(hb4 + t);
            ((float4*)hs)[t] = v;
        }
        __syncthreads();
    }
    for(int idx=t; idx<512; idx+=192){
        int b2 = idx&1, j = idx>>1;
        g_h[(2*p+b2)*HH + j] = hs[idx];
    }
}

// ---------------- MLP head ----------------
__global__ void k_mlp(const float* __restrict__ b0, const float* __restrict__ b1,
                      const float* __restrict__ b2, const float* __restrict__ b3,
                      float* __restrict__ out){
    int b = blockIdx.x; int t = threadIdx.x; // 256
    __shared__ float va[FHD], vb[FHD];
    va[t] = g_h[b*HH + t];
    __syncthreads();
    float acc = b0[t];
    #pragma unroll 8
    for(int j=0;j<HH;j++) acc += va[j]*g_fc0T[j*FHD + t];
    vb[t] = fmaxf(acc, 0.f);
    __syncthreads();
    acc = b1[t];
    #pragma unroll 8
    for(int j=0;j<FHD;j++) acc += vb[j]*g_fc1T[j*FHD + t];
    va[t] = fmaxf(acc, 0.f);
    __syncthreads();
    acc = b2[t];
    #pragma unroll 8
    for(int j=0;j<FHD;j++) acc += va[j]*g_fc2T[j*FHD + t];
    vb[t] = fmaxf(acc, 0.f);
    __syncthreads();
    if(t < 64){
        float a = b3[t];
        #pragma unroll 8
        for(int j=0;j<FHD;j++) a += vb[j]*g_fc3T[j*64 + t];
        out[b*64 + t] = a;
    }
}

// ---------------- launch ----------------
extern "C" void kernel_launch(void* const* d_in, const int* in_sizes, int n_in,
                              void* d_out, int out_size){
    const float* x        = (const float*)d_in[0];
    const float* conv_w   = (const float*)d_in[1];
    const float* conv_b   = (const float*)d_in[2];
    const float* flw      = (const float*)d_in[3];
    const float* flb      = (const float*)d_in[4];
    const float* fa       = (const float*)d_in[5];
    const float* fbias    = (const float*)d_in[6];
    const float* tlw      = (const float*)d_in[7];
    const float* tlb      = (const float*)d_in[8];
    const float* ta       = (const float*)d_in[9];
    const float* tbias    = (const float*)d_in[10];
    const float* wih      = (const float*)d_in[11];
    const float* whh      = (const float*)d_in[12];
    const float* bih      = (const float*)d_in[13];
    const float* bhh      = (const float*)d_in[14];
    const float* fc0_w    = (const float*)d_in[15];
    const float* fc0_b    = (const float*)d_in[16];
    const float* fc1_w    = (const float*)d_in[17];
    const float* fc1_b    = (const float*)d_in[18];
    const float* fc2_w    = (const float*)d_in[19];
    const float* fc2_b    = (const float*)d_in[20];
    const float* fc3_w    = (const float*)d_in[21];
    const float* fc3_b    = (const float*)d_in[22];
    float* out = (float*)d_out;

    k_prep<<<2352, 256>>>(conv_w, tlw, wih, whh, fc0_w, fc1_w, fc2_w, fc3_w);
    k_u<<<1, 128>>>(flw, flb, fa);
    k_conv<<<dim3(32, 64), 64>>>(x, conv_b);
    k_s<<<64, 256>>>();
    k_feat<<<64, 128>>>(fbias);
    k_pq<<<dim3(16, 64), 128>>>(tlb);
    k_temp<<<dim3(16, 64), 128>>>(ta, tbias);
    k_gi<<<512, 256>>>(bih);
    k_gru<<<128, 192>>>(bhh);
    k_mlp<<<64, 256>>>(fc0_b, fc1_b, fc2_b, fc3_b, out);
}

// round 5
// speedup vs baseline: 4.2610x; 2.4798x over previous
#include <cuda_runtime.h>
#include <math.h>
#include <stdint.h>

#define BB  64
#define WW  128
#define KK  64
#define KSZ 7
#define EFD 128
#define ETD 128
#define HH  256
#define FHD 256
#define G3  768   // 3*H
#define ZC  192   // 3*K

// ---------------- scratch (static device globals; no runtime alloc) ----------------
__device__ __align__(16) float g_y[BB*WW*KK];
__device__ float g_s1[BB*KK];
__device__ float g_s2[BB*KK];
__device__ __align__(16) float g_hfeat[BB*WW*KK];
__device__ __align__(16) float g_htemp[BB*WW*KK];
__device__ __align__(16) float g_p[BB*WW*ETD];
__device__ __align__(16) float g_q[BB*WW*ETD];
__device__ __align__(16) float g_gi[BB*WW*G3];
__device__ float g_h[BB*HH];
__device__ __align__(16) float g_cwT[KSZ*KK*KK];   // [s][i][k]
__device__ __align__(16) float g_tlwT[ETD*ETD];    // [c][e]
__device__ __align__(16) float g_wihT[ZC*G3];      // [c][o]
__device__ __align__(16) float g_whhS[4*128*192*2]; // [slice][jp][row 0..191][j-parity]
__device__ __align__(16) float g_fc0T[FHD*FHD];
__device__ __align__(16) float g_fc1T[FHD*FHD];
__device__ __align__(16) float g_fc2T[FHD*FHD];
__device__ __align__(16) float g_fc3T[FHD*KK];
__device__ float g_u1[WW];
__device__ float g_u2[WW];
__device__ float g_c12[2];

__device__ __forceinline__ float sigm(float x){ return 1.f/(1.f+__expf(-x)); }
__device__ __forceinline__ float lrelu(float v){ return fmaxf(v, 0.2f*v); } // ALPHA=0.2<1

__device__ __forceinline__ uint32_t smem_u32(const void* p){
    uint32_t a;
    asm("{ .reg .u64 t0; cvta.to.shared.u64 t0, %1; cvt.u32.u64 %0, t0; }" : "=r"(a) : "l"(p));
    return a;
}
__device__ __forceinline__ void fma2(unsigned long long& a, unsigned long long w, unsigned long long h){
    asm("fma.rn.f32x2 %0, %1, %2, %0;" : "+l"(a) : "l"(w), "l"(h));
}
__device__ __forceinline__ float ull_sum(unsigned long long v){
    unsigned lo, hi;
    asm("mov.b64 {%0,%1}, %2;" : "=r"(lo), "=r"(hi) : "l"(v));
    return __uint_as_float(lo) + __uint_as_float(hi);
}
__device__ __forceinline__ void mbar_init(uint32_t mb, uint32_t cnt){
    asm volatile("mbarrier.init.shared.b64 [%0], %1;" :: "r"(mb), "r"(cnt) : "memory");
}
__device__ __forceinline__ void mbar_expect(uint32_t mb, uint32_t tx){
    asm volatile("mbarrier.arrive.expect_tx.shared.b64 _, [%0], %1;" :: "r"(mb), "r"(tx) : "memory");
}
__device__ __forceinline__ void mbar_wait(uint32_t mb, int parity){
    asm volatile(
        "{\n\t.reg .pred P1;\n\t"
        "WL_%=:\n\t"
        "mbarrier.try_wait.parity.acquire.cta.shared::cta.b64 P1, [%0], %1, 0x989680;\n\t"
        "@P1 bra.uni WD_%=;\n\t"
        "bra.uni WL_%=;\n\t"
        "WD_%=:\n\t}"
        :: "r"(mb), "r"(parity) : "memory");
}
__device__ __forceinline__ uint32_t mapa_u32(uint32_t a, uint32_t rank){
    uint32_t r;
    asm("mapa.shared::cluster.u32 %0, %1, %2;" : "=r"(r) : "r"(a), "r"(rank));
    return r;
}
__device__ __forceinline__ void dsmem_bulk(uint32_t dst, uint32_t src, uint32_t bytes, uint32_t rbar){
    asm volatile("cp.async.bulk.shared::cluster.shared::cta.mbarrier::complete_tx::bytes [%0], [%1], %2, [%3];"
                 :: "r"(dst), "r"(src), "r"(bytes), "r"(rbar) : "memory");
}

// ---------------- weight reshapes / transposes ----------------
__global__ void k_prep(const float* __restrict__ conv_w, const float* __restrict__ tlw,
                       const float* __restrict__ wih, const float* __restrict__ whh,
                       const float* __restrict__ fc0, const float* __restrict__ fc1,
                       const float* __restrict__ fc2, const float* __restrict__ fc3){
    int idx = blockIdx.x*blockDim.x + threadIdx.x;
    // conv_w: (64,64,7) -> [s][i][k]
    if(idx < 28672){
        int k = idx/448; int rem = idx - k*448; int i = rem/7; int s = rem - i*7;
        g_cwT[(s*64+i)*64 + k] = conv_w[idx];
        return;
    }
    idx -= 28672;
    if(idx < 16384){ // temp_lin_w (128,128) -> [c][e]
        int e = idx>>7, c = idx&127;
        g_tlwT[c*128 + e] = tlw[idx];
        return;
    }
    idx -= 16384;
    if(idx < 147456){ // gru_wih (768,192) -> [c][o]
        int o = idx/192, c = idx - o*192;
        g_wihT[c*768 + o] = wih[idx];
        return;
    }
    idx -= 147456;
    if(idx < 196608){ // gru_whh (768,256) -> [s][jp][r][par]
        int o = idx>>8, j = idx&255;
        int g = o>>8;          // gate 0..2
        int ou = o&255;        // hidden unit
        int s = ou>>6, ol = ou&63;
        int r = g*64 + ol;     // row within slice 0..191
        int jp = j>>1, par = j&1;
        g_whhS[((s*128 + jp)*192 + r)*2 + par] = whh[idx];
        return;
    }
    idx -= 196608;
    if(idx < 65536){ int o = idx>>8, j = idx&255; g_fc0T[j*256+o] = fc0[idx]; return; }
    idx -= 65536;
    if(idx < 65536){ int o = idx>>8, j = idx&255; g_fc1T[j*256+o] = fc1[idx]; return; }
    idx -= 65536;
    if(idx < 65536){ int o = idx>>8, j = idx&255; g_fc2T[j*256+o] = fc2[idx]; return; }
    idx -= 65536;
    if(idx < 16384){ int o = idx>>8, j = idx&255; g_fc3T[j*64+o] = fc3[idx]; return; } // fc3 (64,256)
}

// u1[w] = sum_e flw[e,w]*fa[e];  u2 with fa[EF+e];  c1/c2 from bias (linearity of s1/s2)
__global__ void k_u(const float* __restrict__ flw, const float* __restrict__ flb,
                    const float* __restrict__ fa){
    int t = threadIdx.x; // 128
    float a1=0.f, a2=0.f;
    for(int e=0;e<EFD;e++){ float w = flw[e*WW + t]; a1 += w*fa[e]; a2 += w*fa[EFD+e]; }
    g_u1[t]=a1; g_u2[t]=a2;
    if(t==0){ float c=0.f; for(int e=0;e<EFD;e++) c += flb[e]*fa[e];     g_c12[0]=c; }
    if(t==1){ float c=0.f; for(int e=0;e<EFD;e++) c += flb[e]*fa[EFD+e]; g_c12[1]=c; }
}

// ---------------- conv1d (pad=3) + relu -> y[b,w,k] ; 16 w per block ----------------
__global__ void k_conv(const float* __restrict__ x, const float* __restrict__ conv_b){
    int b = blockIdx.y; int w0 = blockIdx.x*16;
    int t = threadIdx.x; // 128
    int k = t&63, half = t>>6;
    __shared__ float xs[22*64];
    for(int i=t; i<22*64; i+=128){
        int row = w0-3+(i>>6);
        xs[i] = (row>=0 && row<WW) ? x[(b*WW+row)*KK + (i&63)] : 0.f;
    }
    __syncthreads();
    float bias = conv_b[k];
    float a[8];
    #pragma unroll
    for(int r=0;r<8;r++) a[r]=bias;
    #pragma unroll
    for(int s=0;s<KSZ;s++){
        #pragma unroll 8
        for(int i=0;i<KK;i++){
            float cw = g_cwT[(s*64+i)*64 + k];
            #pragma unroll
            for(int r=0;r<8;r++) a[r] += xs[(half*8+r+s)*64+i]*cw;
        }
    }
    #pragma unroll
    for(int r=0;r<8;r++)
        g_y[(b*WW + w0 + half*8 + r)*KK + k] = fmaxf(a[r], 0.f);
}

// ---------------- s1,s2 (collapsed Wx GEMM) ----------------
__global__ void k_s(void){
    int b = blockIdx.x; int t = threadIdx.x; // 256
    __shared__ float u1s[WW], u2s[WW], r1[256], r2[256];
    if(t<128){ u1s[t]=g_u1[t]; u2s[t]=g_u2[t]; }
    __syncthreads();
    int k = t&63, wq = t>>6;
    float a1=0.f, a2=0.f;
    #pragma unroll 8
    for(int w=wq*32; w<wq*32+32; w++){
        float yv = g_y[(b*WW+w)*KK + k];
        a1 += yv*u1s[w]; a2 += yv*u2s[w];
    }
    r1[t]=a1; r2[t]=a2;
    __syncthreads();
    if(t<64){
        g_s1[b*KK+t] = r1[t]+r1[t+64]+r1[t+128]+r1[t+192] + g_c12[0];
        g_s2[b*KK+t] = r2[t]+r2[t+64]+r2[t+128]+r2[t+192] + g_c12[1];
    }
}

// ---------------- feature attention + h_feat ----------------
__global__ void k_feat(const float* __restrict__ feat_bias){
    int b = blockIdx.x; int t = threadIdx.x; // 128
    __shared__ float ys[WW*KK];    // 32KB  ys[w*64+j]
    __shared__ float att[KK*KK];   // 16KB  att[j*64+i]
    for(int it=0; it<64; it++){ int idx = it*128+t; ys[idx] = g_y[b*WW*KK + idx]; }
    __syncthreads();
    int lane = t&31, wd = t>>5;
    for(int r=0;r<16;r++){
        int i = wd*16 + r;
        float s1v = g_s1[b*64+i];
        int j0 = lane, j1 = lane+32;
        float v0 = lrelu(s1v + g_s2[b*64+j0]) + feat_bias[i*64+j0];
        float v1 = lrelu(s1v + g_s2[b*64+j1]) + feat_bias[i*64+j1];
        float m = fmaxf(v0,v1);
        #pragma unroll
        for(int off=16;off;off>>=1) m = fmaxf(m, __shfl_xor_sync(0xffffffffu, m, off));
        float e0 = __expf(v0-m), e1 = __expf(v1-m);
        float ssum = e0+e1;
        #pragma unroll
        for(int off=16;off;off>>=1) ssum += __shfl_xor_sync(0xffffffffu, ssum, off);
        float inv = 1.f/ssum;
        att[j0*64+i] = e0*inv;
        att[j1*64+i] = e1*inv;
    }
    __syncthreads();
    int i = t&63, wofs = t>>6;
    for(int wl=0; wl<64; wl++){
        int w = wl*2 + wofs;
        float acc = 0.f;
        #pragma unroll 8
        for(int j=0;j<64;j++) acc += att[j*64+i]*ys[w*64+j];
        g_hfeat[(b*WW+w)*KK + i] = sigm(acc);
    }
}

// ---------------- p,q (temp_lin_b folded into p) ----------------
__global__ void k_pq(const float* __restrict__ tlb){
    int b = blockIdx.y; int w0 = blockIdx.x*8; int t = threadIdx.x; // 128 (= e)
    __shared__ float ys[8*64];
    #pragma unroll
    for(int r=0;r<4;r++){ int idx = r*128+t; ys[idx] = g_y[(b*WW+w0)*KK + idx]; }
    __syncthreads();
    float pb = tlb[t];
    float ap[8], aq[8];
    #pragma unroll
    for(int r=0;r<8;r++){ ap[r]=pb; aq[r]=0.f; }
    for(int c=0;c<64;c++){
        float wp = g_tlwT[c*ETD + t];
        float wq = g_tlwT[(64+c)*ETD + t];
        #pragma unroll
        for(int r=0;r<8;r++){ float yv = ys[r*64+c]; ap[r]+=yv*wp; aq[r]+=yv*wq; }
    }
    #pragma unroll
    for(int r=0;r<8;r++){
        g_p[(b*WW+w0+r)*ETD + t] = ap[r];
        g_q[(b*WW+w0+r)*ETD + t] = aq[r];
    }
}

// ---------------- temporal attention + h_temp (8 i's per block) ----------------
__global__ void k_temp(const float* __restrict__ temp_a, const float* __restrict__ temp_bias){
    int i0 = blockIdx.x*8; int b = blockIdx.y; int t = threadIdx.x; // 128 (= j)
    __shared__ __align__(16) float psst[8*128];
    __shared__ float tass[128];
    __shared__ __align__(16) float atts[128*8];
    __shared__ float wr[8*4];
    __shared__ float hb[64*8];
    tass[t] = temp_a[t];
    #pragma unroll
    for(int r=0;r<8;r++) psst[r*128+t] = g_p[(b*WW+i0+r)*ETD + t];
    __syncthreads();
    const float4* q4 = (const float4*)(g_q + (size_t)(b*WW+t)*ETD);
    float ej[8];
    #pragma unroll
    for(int i=0;i<8;i++) ej[i] = temp_bias[(i0+i)*WW + t];
    for(int c=0;c<32;c++){
        float4 qv = q4[c];
        float ta0=tass[4*c], ta1=tass[4*c+1], ta2=tass[4*c+2], ta3=tass[4*c+3];
        #pragma unroll
        for(int i=0;i<8;i++){
            const float* pp = psst + i*128 + 4*c;
            float v;
            v = pp[0]+qv.x; ej[i] += lrelu(v)*ta0;
            v = pp[1]+qv.y; ej[i] += lrelu(v)*ta1;
            v = pp[2]+qv.z; ej[i] += lrelu(v)*ta2;
            v = pp[3]+qv.w; ej[i] += lrelu(v)*ta3;
        }
    }
    int lane = t&31, wd = t>>5;
    #pragma unroll
    for(int i=0;i<8;i++){
        float m = ej[i];
        #pragma unroll
        for(int off=16;off;off>>=1) m = fmaxf(m, __shfl_xor_sync(0xffffffffu, m, off));
        if(lane==0) wr[i*4+wd]=m;
    }
    __syncthreads();
    float mx[8];
    #pragma unroll
    for(int i=0;i<8;i++) mx[i] = fmaxf(fmaxf(wr[i*4],wr[i*4+1]), fmaxf(wr[i*4+2],wr[i*4+3]));
    __syncthreads();
    #pragma unroll
    for(int i=0;i<8;i++){
        float e = __expf(ej[i]-mx[i]); ej[i]=e;
        float ss = e;
        #pragma unroll
        for(int off=16;off;off>>=1) ss += __shfl_xor_sync(0xffffffffu, ss, off);
        if(lane==0) wr[i*4+wd]=ss;
    }
    __syncthreads();
    #pragma unroll
    for(int i=0;i<8;i++){
        float ss = wr[i*4]+wr[i*4+1]+wr[i*4+2]+wr[i*4+3];
        atts[t*8+i] = ej[i]/ss;
    }
    __syncthreads();
    int k = t&63, half = t>>6;
    float acc[8];
    #pragma unroll
    for(int i=0;i<8;i++) acc[i]=0.f;
    for(int j=0;j<64;j++){
        int jj = half*64+j;
        float yv = g_y[(b*WW+jj)*KK + k];
        const float4* a4 = (const float4*)(atts + jj*8);
        float4 aA = a4[0], aB = a4[1];
        acc[0]+=aA.x*yv; acc[1]+=aA.y*yv; acc[2]+=aA.z*yv; acc[3]+=aA.w*yv;
        acc[4]+=aB.x*yv; acc[5]+=aB.y*yv; acc[6]+=aB.z*yv; acc[7]+=aB.w*yv;
    }
    if(half==1){
        #pragma unroll
        for(int i=0;i<8;i++) hb[k*8+i]=acc[i];
    }
    __syncthreads();
    if(half==0){
        #pragma unroll
        for(int i=0;i<8;i++){
            float v = acc[i] + hb[k*8+i];
            g_htemp[(b*WW+i0+i)*KK + k] = sigm(v);
        }
    }
}

// ---------------- gi = Z @ wih^T + bih  (packed f32x2 FMA, 32-row tiles) ----------------
__global__ __launch_bounds__(256) void k_gi(const float* __restrict__ bih){
    int m0 = blockIdx.x*32; int t = threadIdx.x; // 256
    __shared__ __align__(16) float zs[ZC*34];    // [c][32 rows, pad 34]
    #pragma unroll
    for(int it=0; it<24; it++){
        int idx = it*256 + t;                // 6144 total
        int r = idx/ZC, c = idx - r*ZC;
        int m = m0 + r; int bb = m>>7; int tt = m&127;
        int base = (bb*WW+tt)*KK;
        float v;
        if(c < 64)       v = g_y[base + c];
        else if(c < 128) v = g_hfeat[base + c-64];
        else             v = g_htemp[base + c-128];
        zs[c*34 + r] = v;
    }
    __syncthreads();
    #pragma unroll
    for(int chunk=0; chunk<3; chunk++){
        int col = chunk*256 + t;
        float bv = bih[col];
        unsigned long long acc[16];
        unsigned long long bb2;
        asm("mov.b64 %0, {%1, %1};" : "=l"(bb2) : "r"(__float_as_uint(bv)));
        #pragma unroll
        for(int i=0;i<16;i++) acc[i] = bb2;
        for(int c=0;c<ZC;c++){
            float w = g_wihT[c*G3 + col];
            unsigned long long ww;
            asm("mov.b64 %0, {%1, %1};" : "=l"(ww) : "r"(__float_as_uint(w)));
            const unsigned long long* z2 = (const unsigned long long*)(zs + c*34);
            #pragma unroll
            for(int i=0;i<16;i++){
                asm("fma.rn.f32x2 %0, %1, %2, %0;" : "+l"(acc[i]) : "l"(ww), "l"(z2[i]));
            }
        }
        #pragma unroll
        for(int i=0;i<16;i++){
            unsigned lo, hi;
            asm("mov.b64 {%0, %1}, %2;" : "=r"(lo), "=r"(hi) : "l"(acc[i]));
            g_gi[(size_t)(m0+2*i  )*G3 + col] = __uint_as_float(lo);
            g_gi[(size_t)(m0+2*i+1)*G3 + col] = __uint_as_float(hi);
        }
    }
}

// ---------------- GRU: 32 clusters x 4 slice-CTAs, DSMEM h exchange ----------------
__global__ __launch_bounds__(192) __cluster_dims__(4,1,1) void k_gru(const float* __restrict__ bhh){
    int t = threadIdx.x;       // 192
    int p = blockIdx.x >> 2;   // batch-pair group
    uint32_t s;                // slice = rank in cluster
    asm("mov.u32 %0, %%cluster_ctarank;" : "=r"(s));
    __shared__ __align__(16) float hs[2][2][256];       // [buf][batch][j]
    __shared__ __align__(16) float part[4*192*2];       // [jg][row][batch]
    __shared__ __align__(16) float stg[2][2][64];       // [buf][batch][unit]
    __shared__ __align__(8)  unsigned long long mbar[2];
    uint32_t mb0 = smem_u32(&mbar[0]), mb1 = smem_u32(&mbar[1]);
    for(int i=t;i<1024;i+=192) ((float*)hs)[i]=0.f;
    if(t==0){ mbar_init(mb0,1); mbar_init(mb1,1); }
    __syncthreads();
    asm volatile("barrier.cluster.arrive.aligned;" ::: "memory");
    asm volatile("barrier.cluster.wait.aligned;" ::: "memory");

    int jg = t/48, rg = t - jg*48;
    const ulonglong2* wb = ((const ulonglong2*)g_whhS) + ((s*128 + (uint32_t)jg*32)*96 + 2*(uint32_t)rg);
    ulonglong2 wr2[32];
    #pragma unroll
    for(int jl=0;jl<16;jl++){ wr2[2*jl] = wb[jl*96]; wr2[2*jl+1] = wb[jl*96+1]; }

    int ol = t&63, bsel = (t>>6)&1;
    float bhr=0.f, bhz=0.f, bhn=0.f;
    if(t<128){
        bhr = bhh[      64*s+ol];
        bhz = bhh[256 + 64*s+ol];
        bhn = bhh[512 + 64*s+ol];
    }
    const float* gib0 = g_gi + (size_t)(2*p+bsel)*WW*G3 + s*64 + ol;
    int ph0=0, ph1=0;

    for(int step=0; step<WW; step++){
        int cb = step&1, nb = cb^1;
        if(step>0){
            if(cb==0){ mbar_wait(mb0, ph0); ph0^=1; }
            else     { mbar_wait(mb1, ph1); ph1^=1; }
        }
        if(t==0 && step<127) mbar_expect(nb==0? mb0 : mb1, 2048);

        unsigned long long acc[8];
        #pragma unroll
        for(int i=0;i<8;i++) acc[i]=0ull;
        const unsigned long long* h0 = (const unsigned long long*)&hs[cb][0][jg*64];
        const unsigned long long* h1 = (const unsigned long long*)&hs[cb][1][jg*64];
        #pragma unroll
        for(int jl=0;jl<16;jl++){
            unsigned long long hb0 = h0[jl], hb1 = h1[jl];
            fma2(acc[0], wr2[2*jl].x,   hb0); fma2(acc[1], wr2[2*jl].x,   hb1);
            fma2(acc[2], wr2[2*jl].y,   hb0); fma2(acc[3], wr2[2*jl].y,   hb1);
            fma2(acc[4], wr2[2*jl+1].x, hb0); fma2(acc[5], wr2[2*jl+1].x, hb1);
            fma2(acc[6], wr2[2*jl+1].y, hb0); fma2(acc[7], wr2[2*jl+1].y, hb1);
        }
        #pragma unroll
        for(int jl=16;jl<32;jl++){
            ulonglong2 wa = __ldg(wb + jl*96);
            ulonglong2 wc = __ldg(wb + jl*96 + 1);
            unsigned long long hb0 = h0[jl], hb1 = h1[jl];
            fma2(acc[0], wa.x, hb0); fma2(acc[1], wa.x, hb1);
            fma2(acc[2], wa.y, hb0); fma2(acc[3], wa.y, hb1);
            fma2(acc[4], wc.x, hb0); fma2(acc[5], wc.x, hb1);
            fma2(acc[6], wc.y, hb0); fma2(acc[7], wc.y, hb1);
        }
        int pb = (jg*192 + 4*rg)*2;
        #pragma unroll
        for(int i=0;i<4;i++){
            part[pb + i*2    ] = ull_sum(acc[i*2  ]);
            part[pb + i*2 + 1] = ull_sum(acc[i*2+1]);
        }
        __syncthreads();
        if(t < 128){
            float ghr=bhr, ghz=bhz, ghn=bhn;
            #pragma unroll
            for(int g4=0; g4<4; g4++){
                ghr += part[(g4*192 +       ol)*2 + bsel];
                ghz += part[(g4*192 +  64 + ol)*2 + bsel];
                ghn += part[(g4*192 + 128 + ol)*2 + bsel];
            }
            const float* gib = gib0 + (size_t)step*G3;
            float gr = __ldcg(gib);
            float gz = __ldcg(gib+256);
            float gn = __ldcg(gib+512);
            float hold = hs[cb][bsel][64*s+ol];
            float r  = sigm(gr+ghr);
            float zg = sigm(gz+ghz);
            float n  = tanhf(gn + r*ghn);
            float hnew = n + zg*(hold - n);
            if(step==127) g_h[(size_t)(2*p+bsel)*HH + 64*s + ol] = hnew;
            else          stg[cb][bsel][ol] = hnew;
        }
        __syncthreads();
        if(t==0 && step<127){
            asm volatile("fence.proxy.async.shared::cta;" ::: "memory");
            uint32_t src0 = smem_u32(&stg[cb][0][0]);
            uint32_t src1 = smem_u32(&stg[cb][1][0]);
            uint32_t d0l  = smem_u32(&hs[nb][0][s*64]);
            uint32_t d1l  = smem_u32(&hs[nb][1][s*64]);
            uint32_t mbn  = nb==0 ? mb0 : mb1;
            #pragma unroll
            for(uint32_t tr=0; tr<4; tr++){
                uint32_t rb = mapa_u32(mbn, tr);
                dsmem_bulk(mapa_u32(d0l, tr), src0, 256, rb);
                dsmem_bulk(mapa_u32(d1l, tr), src1, 256, rb);
            }
        }
    }
}

// ---------------- MLP head ----------------
__global__ void k_mlp(const float* __restrict__ b0, const float* __restrict__ b1,
                      const float* __restrict__ b2, const float* __restrict__ b3,
                      float* __restrict__ out){
    int b = blockIdx.x; int t = threadIdx.x; // 256
    __shared__ float va[FHD], vb[FHD];
    va[t] = g_h[b*HH + t];
    __syncthreads();
    float acc = b0[t];
    #pragma unroll 8
    for(int j=0;j<HH;j++) acc += va[j]*g_fc0T[j*FHD + t];
    vb[t] = fmaxf(acc, 0.f);
    __syncthreads();
    acc = b1[t];
    #pragma unroll 8
    for(int j=0;j<FHD;j++) acc += vb[j]*g_fc1T[j*FHD + t];
    va[t] = fmaxf(acc, 0.f);
    __syncthreads();
    acc = b2[t];
    #pragma unroll 8
    for(int j=0;j<FHD;j++) acc += va[j]*g_fc2T[j*FHD + t];
    vb[t] = fmaxf(acc, 0.f);
    __syncthreads();
    if(t < 64){
        float a = b3[t];
        #pragma unroll 8
        for(int j=0;j<FHD;j++) a += vb[j]*g_fc3T[j*64 + t];
        out[b*64 + t] = a;
    }
}

// ---------------- launch ----------------
extern "C" void kernel_launch(void* const* d_in, const int* in_sizes, int n_in,
                              void* d_out, int out_size){
    const float* x        = (const float*)d_in[0];
    const float* conv_w   = (const float*)d_in[1];
    const float* conv_b   = (const float*)d_in[2];
    const float* flw      = (const float*)d_in[3];
    const float* flb      = (const float*)d_in[4];
    const float* fa       = (const float*)d_in[5];
    const float* fbias    = (const float*)d_in[6];
    const float* tlw      = (const float*)d_in[7];
    const float* tlb      = (const float*)d_in[8];
    const float* ta       = (const float*)d_in[9];
    const float* tbias    = (const float*)d_in[10];
    const float* wih      = (const float*)d_in[11];
    const float* whh      = (const float*)d_in[12];
    const float* bih      = (const float*)d_in[13];
    const float* bhh      = (const float*)d_in[14];
    const float* fc0_w    = (const float*)d_in[15];
    const float* fc0_b    = (const float*)d_in[16];
    const float* fc1_w    = (const float*)d_in[17];
    const float* fc1_b    = (const float*)d_in[18];
    const float* fc2_w    = (const float*)d_in[19];
    const float* fc2_b    = (const float*)d_in[20];
    const float* fc3_w    = (const float*)d_in[21];
    const float* fc3_b    = (const float*)d_in[22];
    float* out = (float*)d_out;

    k_prep<<<2352, 256>>>(conv_w, tlw, wih, whh, fc0_w, fc1_w, fc2_w, fc3_w);
    k_u<<<1, 128>>>(flw, flb, fa);
    k_conv<<<dim3(8, 64), 128>>>(x, conv_b);
    k_s<<<64, 256>>>();
    k_feat<<<64, 128>>>(fbias);
    k_pq<<<dim3(16, 64), 128>>>(tlb);
    k_temp<<<dim3(16, 64), 128>>>(ta, tbias);
    k_gi<<<256, 256>>>(bih);
    k_gru<<<128, 192>>>(bhh);
    k_mlp<<<64, 256>>>(fc0_b, fc1_b, fc2_b, fc3_b, out);
}

// round 6
// speedup vs baseline: 4.6261x; 1.0857x over previous
#include <cuda_runtime.h>
#include <math.h>
#include <stdint.h>

#define BB  64
#define WW  128
#define KK  64
#define KSZ 7
#define EFD 128
#define ETD 128
#define HH  256
#define FHD 256
#define G3  768   // 3*H
#define ZC  192   // 3*K

// ---------------- scratch (static device globals; no runtime alloc) ----------------
__device__ __align__(16) float g_y[BB*WW*KK];
__device__ __align__(16) float g_hfeat[BB*WW*KK];
__device__ __align__(16) float g_htemp[BB*WW*KK];
__device__ __align__(16) float g_p[BB*WW*ETD];
__device__ __align__(16) float g_q[BB*WW*ETD];
__device__ __align__(16) float g_gi[BB*WW*G3];
__device__ float g_h[BB*HH];
__device__ __align__(16) float g_cwT[KSZ*KK*KK];   // [s][i][k]
__device__ __align__(16) float g_tlwT[ETD*ETD];    // [c][e]
__device__ __align__(16) float g_wihT[ZC*G3];      // [c][o]
__device__ __align__(16) float g_whhS[4*128*192*2]; // [slice][jp][row 0..191][j-parity]
__device__ __align__(16) float g_fc0T[FHD*FHD];
__device__ __align__(16) float g_fc1T[FHD*FHD];
__device__ __align__(16) float g_fc2T[FHD*FHD];
__device__ __align__(16) float g_fc3T[FHD*KK];
__device__ float g_u1[WW];
__device__ float g_u2[WW];
__device__ float g_c12[2];

__device__ __forceinline__ float sigm(float x){ return 1.f/(1.f+__expf(-x)); }
__device__ __forceinline__ float lrelu(float v){ return fmaxf(v, 0.2f*v); } // ALPHA=0.2<1

__device__ __forceinline__ uint32_t smem_u32(const void* p){
    uint32_t a;
    asm("{ .reg .u64 t0; cvta.to.shared.u64 t0, %1; cvt.u32.u64 %0, t0; }" : "=r"(a) : "l"(p));
    return a;
}
__device__ __forceinline__ void fma2(unsigned long long& a, unsigned long long w, unsigned long long h){
    asm("fma.rn.f32x2 %0, %1, %2, %0;" : "+l"(a) : "l"(w), "l"(h));
}
__device__ __forceinline__ float ull_sum(unsigned long long v){
    unsigned lo, hi;
    asm("mov.b64 {%0,%1}, %2;" : "=r"(lo), "=r"(hi) : "l"(v));
    return __uint_as_float(lo) + __uint_as_float(hi);
}
__device__ __forceinline__ unsigned long long bcast2(float v){
    unsigned long long r;
    asm("mov.b64 %0, {%1, %1};" : "=l"(r) : "r"(__float_as_uint(v)));
    return r;
}
__device__ __forceinline__ void mbar_init(uint32_t mb, uint32_t cnt){
    asm volatile("mbarrier.init.shared.b64 [%0], %1;" :: "r"(mb), "r"(cnt) : "memory");
}
__device__ __forceinline__ void mbar_expect(uint32_t mb, uint32_t tx){
    asm volatile("mbarrier.arrive.expect_tx.shared.b64 _, [%0], %1;" :: "r"(mb), "r"(tx) : "memory");
}
__device__ __forceinline__ void mbar_wait(uint32_t mb, int parity){
    asm volatile(
        "{\n\t.reg .pred P1;\n\t"
        "WL_%=:\n\t"
        "mbarrier.try_wait.parity.acquire.cta.shared::cta.b64 P1, [%0], %1, 0x989680;\n\t"
        "@P1 bra.uni WD_%=;\n\t"
        "bra.uni WL_%=;\n\t"
        "WD_%=:\n\t}"
        :: "r"(mb), "r"(parity) : "memory");
}
__device__ __forceinline__ uint32_t mapa_u32(uint32_t a, uint32_t rank){
    uint32_t r;
    asm("mapa.shared::cluster.u32 %0, %1, %2;" : "=r"(r) : "r"(a), "r"(rank));
    return r;
}
__device__ __forceinline__ void dsmem_bulk(uint32_t dst, uint32_t src, uint32_t bytes, uint32_t rbar){
    asm volatile("cp.async.bulk.shared::cluster.shared::cta.mbarrier::complete_tx::bytes [%0], [%1], %2, [%3];"
                 :: "r"(dst), "r"(src), "r"(bytes), "r"(rbar) : "memory");
}

// ---------------- weight reshapes / transposes + u1/u2/c12 ----------------
__global__ void k_prep(const float* __restrict__ conv_w, const float* __restrict__ tlw,
                       const float* __restrict__ wih, const float* __restrict__ whh,
                       const float* __restrict__ fc0, const float* __restrict__ fc1,
                       const float* __restrict__ fc2, const float* __restrict__ fc3,
                       const float* __restrict__ flw, const float* __restrict__ flb,
                       const float* __restrict__ fa){
    int idx = blockIdx.x*blockDim.x + threadIdx.x;
    // conv_w: (64,64,7) -> [s][i][k]
    if(idx < 28672){
        int k = idx/448; int rem = idx - k*448; int i = rem/7; int s = rem - i*7;
        g_cwT[(s*64+i)*64 + k] = conv_w[idx];
        return;
    }
    idx -= 28672;
    if(idx < 16384){ // temp_lin_w (128,128) -> [c][e]
        int e = idx>>7, c = idx&127;
        g_tlwT[c*128 + e] = tlw[idx];
        return;
    }
    idx -= 16384;
    if(idx < 147456){ // gru_wih (768,192) -> [c][o]
        int o = idx/192, c = idx - o*192;
        g_wihT[c*768 + o] = wih[idx];
        return;
    }
    idx -= 147456;
    if(idx < 196608){ // gru_whh (768,256) -> [s][jp][r][par]
        int o = idx>>8, j = idx&255;
        int g = o>>8;          // gate 0..2
        int ou = o&255;        // hidden unit
        int s = ou>>6, ol = ou&63;
        int r = g*64 + ol;     // row within slice 0..191
        int jp = j>>1, par = j&1;
        g_whhS[((s*128 + jp)*192 + r)*2 + par] = whh[idx];
        return;
    }
    idx -= 196608;
    if(idx < 65536){ int o = idx>>8, j = idx&255; g_fc0T[j*256+o] = fc0[idx]; return; }
    idx -= 65536;
    if(idx < 65536){ int o = idx>>8, j = idx&255; g_fc1T[j*256+o] = fc1[idx]; return; }
    idx -= 65536;
    if(idx < 65536){ int o = idx>>8, j = idx&255; g_fc2T[j*256+o] = fc2[idx]; return; }
    idx -= 65536;
    if(idx < 16384){ int o = idx>>8, j = idx&255; g_fc3T[j*64+o] = fc3[idx]; return; } // fc3 (64,256)
    idx -= 16384;
    // u1[w], u2[w], c12
    if(idx < 128){
        float a1=0.f, a2=0.f;
        for(int e=0;e<EFD;e++){ float w = flw[e*WW + idx]; a1 += w*fa[e]; a2 += w*fa[EFD+e]; }
        g_u1[idx]=a1; g_u2[idx]=a2;
        return;
    }
    if(idx==128){ float c=0.f; for(int e=0;e<EFD;e++) c += flb[e]*fa[e];     g_c12[0]=c; return; }
    if(idx==129){ float c=0.f; for(int e=0;e<EFD;e++) c += flb[e]*fa[EFD+e]; g_c12[1]=c; return; }
}

// ---------------- conv1d (pad=3) + relu -> y[b,w,k] ; f32x2 over k-pairs ----------------
__global__ void k_conv(const float* __restrict__ x, const float* __restrict__ conv_b){
    int b = blockIdx.y; int w0 = blockIdx.x*16;
    int t = threadIdx.x; // 128
    int kp = t&31, wq = t>>5;   // kp: k-pair 0..31 ; wq: 0..3 (4 w each)
    __shared__ float xs[22*64];
    for(int i=t; i<22*64; i+=128){
        int row = w0-3+(i>>6);
        xs[i] = (row>=0 && row<WW) ? x[(b*WW+row)*KK + (i&63)] : 0.f;
    }
    __syncthreads();
    unsigned long long acc[4];
    {
        float2 b2 = *(const float2*)(conv_b + 2*kp);
        unsigned long long bb;
        asm("mov.b64 %0, {%1, %2};" : "=l"(bb) : "r"(__float_as_uint(b2.x)), "r"(__float_as_uint(b2.y)));
        #pragma unroll
        for(int r=0;r<4;r++) acc[r]=bb;
    }
    #pragma unroll
    for(int s=0;s<KSZ;s++){
        #pragma unroll 8
        for(int i=0;i<KK;i++){
            unsigned long long cw2 = *(const unsigned long long*)(g_cwT + (s*64+i)*64 + 2*kp);
            #pragma unroll
            for(int r=0;r<4;r++){
                unsigned long long xx = bcast2(xs[(wq*4+r+s)*64 + i]);
                fma2(acc[r], cw2, xx);
            }
        }
    }
    #pragma unroll
    for(int r=0;r<4;r++){
        unsigned lo, hi;
        asm("mov.b64 {%0,%1}, %2;" : "=r"(lo), "=r"(hi) : "l"(acc[r]));
        float2 o;
        o.x = fmaxf(__uint_as_float(lo), 0.f);
        o.y = fmaxf(__uint_as_float(hi), 0.f);
        *(float2*)(g_y + (size_t)(b*WW + w0 + wq*4 + r)*KK + 2*kp) = o;
    }
}

// ---------------- feature attention + h_feat (s1/s2 fused in) ----------------
__global__ __launch_bounds__(256) void k_feat(const float* __restrict__ feat_bias){
    int b = blockIdx.x; int t = threadIdx.x; // 256
    __shared__ float ys[WW*KK];    // 32KB  ys[w*64+j]
    __shared__ float att[KK*KK];   // 16KB  att[j*64+i]
    __shared__ float u1s[WW], u2s[WW];
    __shared__ float r1[256], r2[256];
    __shared__ float s1s[64], s2s[64];
    if(t<128){ u1s[t]=g_u1[t]; u2s[t]=g_u2[t]; }
    for(int it=0; it<32; it++){ int idx = it*256+t; ys[idx] = g_y[b*WW*KK + idx]; }
    __syncthreads();
    // s1/s2 (collapsed Wx GEMM)
    {
        int k = t&63, q = t>>6;
        float a1=0.f, a2=0.f;
        #pragma unroll 8
        for(int w=q*32; w<q*32+32; w++){
            float yv = ys[w*64+k];
            a1 += yv*u1s[w]; a2 += yv*u2s[w];
        }
        r1[t]=a1; r2[t]=a2;
    }
    __syncthreads();
    if(t<64){
        s1s[t] = r1[t]+r1[t+64]+r1[t+128]+r1[t+192] + g_c12[0];
        s2s[t] = r2[t]+r2[t+64]+r2[t+128]+r2[t+192] + g_c12[1];
    }
    __syncthreads();
    // attention rows: 8 warps x 8 i
    int lane = t&31, wd = t>>5;
    #pragma unroll
    for(int r=0;r<8;r++){
        int i = wd*8 + r;
        float s1v = s1s[i];
        int j0 = lane, j1 = lane+32;
        float v0 = lrelu(s1v + s2s[j0]) + feat_bias[i*64+j0];
        float v1 = lrelu(s1v + s2s[j1]) + feat_bias[i*64+j1];
        float m = fmaxf(v0,v1);
        #pragma unroll
        for(int off=16;off;off>>=1) m = fmaxf(m, __shfl_xor_sync(0xffffffffu, m, off));
        float e0 = __expf(v0-m), e1 = __expf(v1-m);
        float ssum = e0+e1;
        #pragma unroll
        for(int off=16;off;off>>=1) ssum += __shfl_xor_sync(0xffffffffu, ssum, off);
        float inv = 1.f/ssum;
        att[j0*64+i] = e0*inv;
        att[j1*64+i] = e1*inv;
    }
    __syncthreads();
    // h_feat: i = t&63, 4 w-offsets, 2-way interleave
    int i = t&63, wofs = t>>6;
    for(int wl=0; wl<16; wl++){
        int wA = (wl*2  )*4 + wofs;
        int wB = (wl*2+1)*4 + wofs;
        float accA = 0.f, accB = 0.f;
        #pragma unroll 8
        for(int j=0;j<64;j++){
            float av = att[j*64+i];
            accA += av*ys[wA*64+j];
            accB += av*ys[wB*64+j];
        }
        g_hfeat[(b*WW+wA)*KK + i] = sigm(accA);
        g_hfeat[(b*WW+wB)*KK + i] = sigm(accB);
    }
}

// ---------------- p,q (temp_lin_b folded into p) ----------------
__global__ void k_pq(const float* __restrict__ tlb){
    int b = blockIdx.y; int w0 = blockIdx.x*8; int t = threadIdx.x; // 128 (= e)
    __shared__ float ys[8*64];
    #pragma unroll
    for(int r=0;r<4;r++){ int idx = r*128+t; ys[idx] = g_y[(b*WW+w0)*KK + idx]; }
    __syncthreads();
    float pb = tlb[t];
    float ap[8], aq[8];
    #pragma unroll
    for(int r=0;r<8;r++){ ap[r]=pb; aq[r]=0.f; }
    for(int c=0;c<64;c++){
        float wp = g_tlwT[c*ETD + t];
        float wq = g_tlwT[(64+c)*ETD + t];
        #pragma unroll
        for(int r=0;r<8;r++){ float yv = ys[r*64+c]; ap[r]+=yv*wp; aq[r]+=yv*wq; }
    }
    #pragma unroll
    for(int r=0;r<8;r++){
        g_p[(b*WW+w0+r)*ETD + t] = ap[r];
        g_q[(b*WW+w0+r)*ETD + t] = aq[r];
    }
}

// ---------------- temporal attention + h_temp (8 i's per block) ----------------
__global__ void k_temp(const float* __restrict__ temp_a, const float* __restrict__ temp_bias){
    int i0 = blockIdx.x*8; int b = blockIdx.y; int t = threadIdx.x; // 128 (= j)
    __shared__ __align__(16) float psst[8*128];
    __shared__ float tass[128];
    __shared__ __align__(16) float atts[128*8];
    __shared__ float wr[8*4];
    __shared__ float hb[64*8];
    tass[t] = temp_a[t];
    #pragma unroll
    for(int r=0;r<8;r++) psst[r*128+t] = g_p[(b*WW+i0+r)*ETD + t];
    __syncthreads();
    const float4* q4 = (const float4*)(g_q + (size_t)(b*WW+t)*ETD);
    float ej[8];
    #pragma unroll
    for(int i=0;i<8;i++) ej[i] = temp_bias[(i0+i)*WW + t];
    for(int c=0;c<32;c++){
        float4 qv = q4[c];
        float ta0=tass[4*c], ta1=tass[4*c+1], ta2=tass[4*c+2], ta3=tass[4*c+3];
        #pragma unroll
        for(int i=0;i<8;i++){
            const float* pp = psst + i*128 + 4*c;
            float v;
            v = pp[0]+qv.x; ej[i] += lrelu(v)*ta0;
            v = pp[1]+qv.y; ej[i] += lrelu(v)*ta1;
            v = pp[2]+qv.z; ej[i] += lrelu(v)*ta2;
            v = pp[3]+qv.w; ej[i] += lrelu(v)*ta3;
        }
    }
    int lane = t&31, wd = t>>5;
    #pragma unroll
    for(int i=0;i<8;i++){
        float m = ej[i];
        #pragma unroll
        for(int off=16;off;off>>=1) m = fmaxf(m, __shfl_xor_sync(0xffffffffu, m, off));
        if(lane==0) wr[i*4+wd]=m;
    }
    __syncthreads();
    float mx[8];
    #pragma unroll
    for(int i=0;i<8;i++) mx[i] = fmaxf(fmaxf(wr[i*4],wr[i*4+1]), fmaxf(wr[i*4+2],wr[i*4+3]));
    __syncthreads();
    #pragma unroll
    for(int i=0;i<8;i++){
        float e = __expf(ej[i]-mx[i]); ej[i]=e;
        float ss = e;
        #pragma unroll
        for(int off=16;off;off>>=1) ss += __shfl_xor_sync(0xffffffffu, ss, off);
        if(lane==0) wr[i*4+wd]=ss;
    }
    __syncthreads();
    #pragma unroll
    for(int i=0;i<8;i++){
        float ss = wr[i*4]+wr[i*4+1]+wr[i*4+2]+wr[i*4+3];
        atts[t*8+i] = ej[i]/ss;
    }
    __syncthreads();
    int k = t&63, half = t>>6;
    float acc[8];
    #pragma unroll
    for(int i=0;i<8;i++) acc[i]=0.f;
    for(int j=0;j<64;j++){
        int jj = half*64+j;
        float yv = g_y[(b*WW+jj)*KK + k];
        const float4* a4 = (const float4*)(atts + jj*8);
        float4 aA = a4[0], aB = a4[1];
        acc[0]+=aA.x*yv; acc[1]+=aA.y*yv; acc[2]+=aA.z*yv; acc[3]+=aA.w*yv;
        acc[4]+=aB.x*yv; acc[5]+=aB.y*yv; acc[6]+=aB.z*yv; acc[7]+=aB.w*yv;
    }
    if(half==1){
        #pragma unroll
        for(int i=0;i<8;i++) hb[k*8+i]=acc[i];
    }
    __syncthreads();
    if(half==0){
        #pragma unroll
        for(int i=0;i<8;i++){
            float v = acc[i] + hb[k*8+i];
            g_htemp[(b*WW+i0+i)*KK + k] = sigm(v);
        }
    }
}

// ---------------- gi = Z @ wih^T + bih  (packed f32x2 FMA, 32-row tiles) ----------------
__global__ __launch_bounds__(256) void k_gi(const float* __restrict__ bih){
    int m0 = blockIdx.x*32; int t = threadIdx.x; // 256
    __shared__ __align__(16) float zs[ZC*34];    // [c][32 rows, pad 34]
    #pragma unroll
    for(int it=0; it<24; it++){
        int idx = it*256 + t;                // 6144 total
        int r = idx/ZC, c = idx - r*ZC;
        int m = m0 + r; int bb = m>>7; int tt = m&127;
        int base = (bb*WW+tt)*KK;
        float v;
        if(c < 64)       v = g_y[base + c];
        else if(c < 128) v = g_hfeat[base + c-64];
        else             v = g_htemp[base + c-128];
        zs[c*34 + r] = v;
    }
    __syncthreads();
    #pragma unroll
    for(int chunk=0; chunk<3; chunk++){
        int col = chunk*256 + t;
        float bv = bih[col];
        unsigned long long acc[16];
        unsigned long long bb2 = bcast2(bv);
        #pragma unroll
        for(int i=0;i<16;i++) acc[i] = bb2;
        for(int c=0;c<ZC;c++){
            unsigned long long ww = bcast2(g_wihT[c*G3 + col]);
            const unsigned long long* z2 = (const unsigned long long*)(zs + c*34);
            #pragma unroll
            for(int i=0;i<16;i++) fma2(acc[i], ww, z2[i]);
        }
        #pragma unroll
        for(int i=0;i<16;i++){
            unsigned lo, hi;
            asm("mov.b64 {%0, %1}, %2;" : "=r"(lo), "=r"(hi) : "l"(acc[i]));
            g_gi[(size_t)(m0+2*i  )*G3 + col] = __uint_as_float(lo);
            g_gi[(size_t)(m0+2*i+1)*G3 + col] = __uint_as_float(hi);
        }
    }
}

// ---------------- GRU: 32 clusters x 4 slice-CTAs, DSMEM h exchange ----------------
__global__ __launch_bounds__(192) __cluster_dims__(4,1,1) void k_gru(const float* __restrict__ bhh){
    int t = threadIdx.x;       // 192
    int p = blockIdx.x >> 2;   // batch-pair group
    uint32_t s;                // slice = rank in cluster
    asm("mov.u32 %0, %%cluster_ctarank;" : "=r"(s));
    __shared__ __align__(16) float hs[2][128][4];       // [buf][jp][b0p0,b0p1,b1p0,b1p1]
    __shared__ float part[4*192*2];                     // [jg][row][batch]
    __shared__ __align__(16) float stg[2][32][4];       // [buf][jp-local][...]
    __shared__ __align__(8)  unsigned long long mbar[2];
    uint32_t mb0 = smem_u32(&mbar[0]), mb1 = smem_u32(&mbar[1]);
    for(int i=t;i<1024;i+=192) ((float*)hs)[i]=0.f;
    if(t==0){ mbar_init(mb0,1); mbar_init(mb1,1); }
    __syncthreads();
    asm volatile("barrier.cluster.arrive.aligned;" ::: "memory");
    asm volatile("barrier.cluster.wait.aligned;" ::: "memory");

    int jg = t/48, rg = t - jg*48;
    const ulonglong2* wb = ((const ulonglong2*)g_whhS) + ((s*128 + (uint32_t)jg*32)*96 + 2*(uint32_t)rg);
    ulonglong2 wr2[32];
    #pragma unroll
    for(int jl=0;jl<16;jl++){ wr2[2*jl] = wb[jl*96]; wr2[2*jl+1] = wb[jl*96+1]; }

    int ol = t&63, bsel = (t>>6)&1;
    float bhr=0.f, bhz=0.f, bhn=0.f;
    if(t<128){
        bhr = bhh[      64*s+ol];
        bhz = bhh[256 + 64*s+ol];
        bhn = bhh[512 + 64*s+ol];
    }
    const float* gib0 = g_gi + (size_t)(2*p+bsel)*WW*G3 + s*64 + ol;
    // prefetch gi for step 0
    float pfr=0.f, pfz=0.f, pfn=0.f;
    if(t<128){ pfr=__ldcg(gib0); pfz=__ldcg(gib0+256); pfn=__ldcg(gib0+512); }
    int ph0=0, ph1=0;

    for(int step=0; step<WW; step++){
        int cb = step&1, nb = cb^1;
        if(step>0){
            if(cb==0){ mbar_wait(mb0, ph0); ph0^=1; }
            else     { mbar_wait(mb1, ph1); ph1^=1; }
        }
        if(t==0 && step<127) mbar_expect(nb==0? mb0 : mb1, 2048);

        unsigned long long acc[8];
        #pragma unroll
        for(int i=0;i<8;i++) acc[i]=0ull;
        const ulonglong2* hcb = ((const ulonglong2*)hs[cb]) + jg*32;
        #pragma unroll
        for(int jl=0;jl<16;jl++){
            ulonglong2 hv = hcb[jl];
            fma2(acc[0], wr2[2*jl].x,   hv.x); fma2(acc[1], wr2[2*jl].x,   hv.y);
            fma2(acc[2], wr2[2*jl].y,   hv.x); fma2(acc[3], wr2[2*jl].y,   hv.y);
            fma2(acc[4], wr2[2*jl+1].x, hv.x); fma2(acc[5], wr2[2*jl+1].x, hv.y);
            fma2(acc[6], wr2[2*jl+1].y, hv.x); fma2(acc[7], wr2[2*jl+1].y, hv.y);
        }
        #pragma unroll
        for(int jl=16;jl<32;jl++){
            ulonglong2 wa = __ldg(wb + jl*96);
            ulonglong2 wc = __ldg(wb + jl*96 + 1);
            ulonglong2 hv = hcb[jl];
            fma2(acc[0], wa.x, hv.x); fma2(acc[1], wa.x, hv.y);
            fma2(acc[2], wa.y, hv.x); fma2(acc[3], wa.y, hv.y);
            fma2(acc[4], wc.x, hv.x); fma2(acc[5], wc.x, hv.y);
            fma2(acc[6], wc.y, hv.x); fma2(acc[7], wc.y, hv.y);
        }
        int pb = (jg*192 + 4*rg)*2;
        #pragma unroll
        for(int i=0;i<4;i++){
            part[pb + i*2    ] = ull_sum(acc[i*2  ]);
            part[pb + i*2 + 1] = ull_sum(acc[i*2+1]);
        }
        __syncthreads();
        if(t < 128){
            float gr=pfr, gz=pfz, gn=pfn;
            if(step<127){   // prefetch next step's gi; latency hides behind exchange + next j-loop
                const float* gnx = gib0 + (size_t)(step+1)*G3;
                pfr=__ldcg(gnx); pfz=__ldcg(gnx+256); pfn=__ldcg(gnx+512);
            }
            float ghr=bhr, ghz=bhz, ghn=bhn;
            #pragma unroll
            for(int g4=0; g4<4; g4++){
                ghr += part[(g4*192 +       ol)*2 + bsel];
                ghz += part[(g4*192 +  64 + ol)*2 + bsel];
                ghn += part[(g4*192 + 128 + ol)*2 + bsel];
            }
            float hold = hs[cb][32*s + (ol>>1)][bsel*2 + (ol&1)];
            float r  = sigm(gr+ghr);
            float zg = sigm(gz+ghz);
            float n  = tanhf(gn + r*ghn);
            float hnew = n + zg*(hold - n);
            if(step==127) g_h[(size_t)(2*p+bsel)*HH + 64*s + ol] = hnew;
            else          stg[cb][ol>>1][bsel*2 + (ol&1)] = hnew;
        }
        __syncthreads();
        if(t<4 && step<127){
            asm volatile("fence.proxy.async.shared::cta;" ::: "memory");
            uint32_t src = smem_u32(&stg[cb][0][0]);
            uint32_t dstl = smem_u32(&hs[nb][32*s][0]);
            uint32_t mbn  = nb==0 ? mb0 : mb1;
            uint32_t tr = (uint32_t)t;
            uint32_t rb = mapa_u32(mbn, tr);
            dsmem_bulk(mapa_u32(dstl, tr), src, 512, rb);
        }
    }
}

// ---------------- MLP head ----------------
__global__ void k_mlp(const float* __restrict__ b0, const float* __restrict__ b1,
                      const float* __restrict__ b2, const float* __restrict__ b3,
                      float* __restrict__ out){
    int b = blockIdx.x; int t = threadIdx.x; // 256
    __shared__ float va[FHD], vb[FHD];
    va[t] = g_h[b*HH + t];
    __syncthreads();
    float p0=0.f,p1=0.f,p2=0.f,p3=0.f;
    #pragma unroll 4
    for(int j=0;j<HH;j+=4){
        p0 += va[j  ]*g_fc0T[(j  )*FHD + t];
        p1 += va[j+1]*g_fc0T[(j+1)*FHD + t];
        p2 += va[j+2]*g_fc0T[(j+2)*FHD + t];
        p3 += va[j+3]*g_fc0T[(j+3)*FHD + t];
    }
    vb[t] = fmaxf(b0[t] + ((p0+p1)+(p2+p3)), 0.f);
    __syncthreads();
    p0=p1=p2=p3=0.f;
    #pragma unroll 4
    for(int j=0;j<FHD;j+=4){
        p0 += vb[j  ]*g_fc1T[(j  )*FHD + t];
        p1 += vb[j+1]*g_fc1T[(j+1)*FHD + t];
        p2 += vb[j+2]*g_fc1T[(j+2)*FHD + t];
        p3 += vb[j+3]*g_fc1T[(j+3)*FHD + t];
    }
    va[t] = fmaxf(b1[t] + ((p0+p1)+(p2+p3)), 0.f);
    __syncthreads();
    p0=p1=p2=p3=0.f;
    #pragma unroll 4
    for(int j=0;j<FHD;j+=4){
        p0 += va[j  ]*g_fc2T[(j  )*FHD + t];
        p1 += va[j+1]*g_fc2T[(j+1)*FHD + t];
        p2 += va[j+2]*g_fc2T[(j+2)*FHD + t];
        p3 += va[j+3]*g_fc2T[(j+3)*FHD + t];
    }
    vb[t] = fmaxf(b2[t] + ((p0+p1)+(p2+p3)), 0.f);
    __syncthreads();
    if(t < 64){
        p0=p1=p2=p3=0.f;
        #pragma unroll 4
        for(int j=0;j<FHD;j+=4){
            p0 += vb[j  ]*g_fc3T[(j  )*64 + t];
            p1 += vb[j+1]*g_fc3T[(j+1)*64 + t];
            p2 += vb[j+2]*g_fc3T[(j+2)*64 + t];
            p3 += vb[j+3]*g_fc3T[(j+3)*64 + t];
        }
        out[b*64 + t] = b3[t] + ((p0+p1)+(p2+p3));
    }
}

// ---------------- launch ----------------
extern "C" void kernel_launch(void* const* d_in, const int* in_sizes, int n_in,
                              void* d_out, int out_size){
    const float* x        = (const float*)d_in[0];
    const float* conv_w   = (const float*)d_in[1];
    const float* conv_b   = (const float*)d_in[2];
    const float* flw      = (const float*)d_in[3];
    const float* flb      = (const float*)d_in[4];
    const float* fa       = (const float*)d_in[5];
    const float* fbias    = (const float*)d_in[6];
    const float* tlw      = (const float*)d_in[7];
    const float* tlb      = (const float*)d_in[8];
    const float* ta       = (const float*)d_in[9];
    const float* tbias    = (const float*)d_in[10];
    const float* wih      = (const float*)d_in[11];
    const float* whh      = (const float*)d_in[12];
    const float* bih      = (const float*)d_in[13];
    const float* bhh      = (const float*)d_in[14];
    const float* fc0_w    = (const float*)d_in[15];
    const float* fc0_b    = (const float*)d_in[16];
    const float* fc1_w    = (const float*)d_in[17];
    const float* fc1_b    = (const float*)d_in[18];
    const float* fc2_w    = (const float*)d_in[19];
    const float* fc2_b    = (const float*)d_in[20];
    const float* fc3_w    = (const float*)d_in[21];
    const float* fc3_b    = (const float*)d_in[22];
    float* out = (float*)d_out;

    k_prep<<<2353, 256>>>(conv_w, tlw, wih, whh, fc0_w, fc1_w, fc2_w, fc3_w, flw, flb, fa);
    k_conv<<<dim3(8, 64), 128>>>(x, conv_b);
    k_feat<<<64, 256>>>(fbias);
    k_pq<<<dim3(16, 64), 128>>>(tlb);
    k_temp<<<dim3(16, 64), 128>>>(ta, tbias);
    k_gi<<<256, 256>>>(bih);
    k_gru<<<128, 192>>>(bhh);
    k_mlp<<<64, 256>>>(fc0_b, fc1_b, fc2_b, fc3_b, out);
}